// round 6
// baseline (speedup 1.0000x reference)
#include <cuda_runtime.h>

#define BB 4
#define CC 64
#define NN 8192
#define SS 2048
#define KNBR 16
#define GG 64

#define OFF_XYZ (4*256*2048)            /* 2097152 */
#define OFF_IDX (OFF_XYZ + 4*3*2048)    /* 2121728 */

#define MUL_F32X2(out, a, b) \
    asm("mul.rn.f32x2 %0, %1, %2;" : "=l"(out) : "l"(a), "l"(b))
#define ADD_F32X2(out, a, b) \
    asm("add.rn.f32x2 %0, %1, %2;" : "=l"(out) : "l"(a), "l"(b))
#define PACK_F32X2(out, lo, hi) \
    asm("mov.b64 %0, {%1, %2};" : "=l"(out) : "f"(lo), "f"(hi))
#define UNPACK_F32X2(lo, hi, in) \
    asm("mov.b64 {%0, %1}, %2;" : "=f"(lo), "=f"(hi) : "l"(in))
#define REDUX_MAX_U32(d, s) \
    asm volatile("redux.sync.max.u32 %0, %1, 0xffffffff;" : "=r"(d) : "r"(s))
#define REDUX_MIN_U32(d, s) \
    asm volatile("redux.sync.min.u32 %0, %1, 0xffffffff;" : "=r"(d) : "r"(s))

// wait on local mbarrier with cluster-scope acquire (DSMEM stores visible)
#define MBAR_WAIT_CL(mbar, par) do {                                          \
    unsigned _m = (mbar), _p = (par), _d;                                     \
    asm volatile("{\n\t.reg .pred p;\n\t"                                     \
        "mbarrier.try_wait.parity.acquire.cluster.shared::cta.b64 p, [%1], %2;\n\t" \
        "selp.b32 %0, 1, 0, p;\n\t}"                                          \
        : "=r"(_d) : "r"(_m), "r"(_p) : "memory");                            \
    if (!_d) {                                                                \
        asm volatile("{\n\t.reg .pred P1;\n\t"                                \
            "WL_%=:\n\t"                                                      \
            "mbarrier.try_wait.parity.acquire.cluster.shared::cta.b64 P1, [%0], %1;\n\t" \
            "@P1 bra.uni WD_%=;\n\t"                                          \
            "bra.uni WL_%=;\n\t"                                              \
            "WD_%=:\n\t}"                                                     \
            :: "r"(_m), "r"(_p) : "memory");                                  \
    }                                                                         \
} while (0)

// store key into remote CTA's slot + release-arrive on its mbarrier
__device__ __forceinline__ void st_arrive_remote(unsigned slotAddr, unsigned mbarAddr,
                                                 unsigned long long key, unsigned r)
{
    asm volatile(
        "{\n\t"
        ".reg .b32 rs, rm;\n\t"
        "mapa.shared::cluster.u32 rs, %0, %2;\n\t"
        "mapa.shared::cluster.u32 rm, %1, %2;\n\t"
        "st.shared::cluster.b64 [rs], %3;\n\t"
        "mbarrier.arrive.release.cluster.shared::cluster.b64 _, [rm];\n\t"
        "}"
        :: "r"(slotAddr), "r"(mbarAddr), "r"(r), "l"(key) : "memory");
}

#define CLUSTER_SYNC_() do {                                        \
    asm volatile("barrier.cluster.arrive.aligned;" ::: "memory");   \
    asm volatile("barrier.cluster.wait.aligned;" ::: "memory");     \
} while (0)

// ---------------- scratch (static device globals; no allocations) ----------
__device__ int   g_sidx[BB*SS];
__device__ float g_sx[BB*CC*SS];
__device__ float g_pn[BB*NN];
__device__ float g_qn[BB*SS];
__device__ float g_D[(size_t)BB*SS*NN];    // 256 MB distance matrix
__device__ int   g_knn[BB*SS*KNBR];

// ============================================================================
// Kernel 1: Farthest point sampling, 4-CTA cluster per batch (16 CTAs total).
// Each CTA owns 2048 contiguous points (4/thread, packed f32x2). Per
// iteration: local exact argmax (redux max + lowest-index redux min), then a
// DSMEM key exchange (u64 = distbits<<32 | (8191-idx)) so every CTA computes
// the identical global winner. Distance arithmetic is bit-identical to the
// reference (no fma contraction, ((dx^2+dy^2)+dz^2), fminf); selection is the
// exact argmax with lowest-index tie-break.
// ============================================================================
__global__ __launch_bounds__(512) __cluster_dims__(4, 1, 1)
void fps_kernel(const float* __restrict__ xyz, float* __restrict__ out)
{
    const int b    = blockIdx.x >> 2;
    const int rank = blockIdx.x & 3;
    const int tid  = threadIdx.x;
    const int lane = tid & 31;
    const int wid  = tid >> 5;
    const float* xb = xyz + (size_t)b * 3 * NN;
    const int base = rank * 2048;

    __shared__ unsigned long long slots[2][4];
    __shared__ unsigned long long mbar;
    __shared__ unsigned swhi[16];
    __shared__ unsigned swbi[16];

    const unsigned mbar_a  = (unsigned)__cvta_generic_to_shared(&mbar);
    const unsigned slots_a = (unsigned)__cvta_generic_to_shared(&slots[0][0]);

    if (tid == 0) {
        asm volatile("mbarrier.init.shared.b64 [%0], 4;" :: "r"(mbar_a) : "memory");
    }
    __syncthreads();
    CLUSTER_SYNC_();          // all mbarriers initialized before any remote arrive

    // my 4 points: indices base+tid, +512, +1024, +1536 (pair jp: n0, n0+512)
    unsigned long long pxp[2], pyp[2], pzp[2];
    float dd[4];
    const float FMAX = __int_as_float(0x7F7FFFFF);
#pragma unroll
    for (int jp = 0; jp < 2; jp++) {
        int n0 = base + tid + 1024 * jp;
        int n1 = n0 + 512;
        PACK_F32X2(pxp[jp], xb[n0],        xb[n1]);
        PACK_F32X2(pyp[jp], xb[NN + n0],   xb[NN + n1]);
        PACK_F32X2(pzp[jp], xb[2*NN + n0], xb[2*NN + n1]);
        dd[2*jp]     = FMAX;
        dd[2*jp + 1] = FMAX;
    }

    if (rank == 0 && tid == 0) {
        g_sidx[b * SS + 0] = 0;
        out[OFF_IDX + b * SS + 0] = 0.0f;
        out[OFF_XYZ + (size_t)(b * 3 + 0) * SS + 0] = xb[0];
        out[OFF_XYZ + (size_t)(b * 3 + 1) * SS + 0] = xb[NN];
        out[OFF_XYZ + (size_t)(b * 3 + 2) * SS + 0] = xb[2*NN];
    }

    float lx = xb[0], ly = xb[NN], lz = xb[2*NN];

    for (int s = 1; s < SS; s++) {
        unsigned long long nlx2, nly2, nlz2;
        {
            float nx = -lx, ny = -ly, nz = -lz;
            PACK_F32X2(nlx2, nx, nx);
            PACK_F32X2(nly2, ny, ny);
            PACK_F32X2(nlz2, nz, nz);
        }

#pragma unroll
        for (int jp = 0; jp < 2; jp++) {
            unsigned long long dx2, dy2, dz2, sx2, sy2, sz2, s12, s22;
            ADD_F32X2(dx2, pxp[jp], nlx2);      // px - lx (exact: px + (-lx))
            ADD_F32X2(dy2, pyp[jp], nly2);
            ADD_F32X2(dz2, pzp[jp], nlz2);
            MUL_F32X2(sx2, dx2, dx2);
            MUL_F32X2(sy2, dy2, dy2);
            MUL_F32X2(sz2, dz2, dz2);
            ADD_F32X2(s12, sx2, sy2);           // (dx^2 + dy^2)
            ADD_F32X2(s22, s12, sz2);           // + dz^2
            float t0, t1;
            UNPACK_F32X2(t0, t1, s22);
            dd[2*jp]     = fminf(dd[2*jp],     t0);
            dd[2*jp + 1] = fminf(dd[2*jp + 1], t1);
        }

        // ---- warp-level exact argmax (lowest index on ties) ----
        float best = fmaxf(fmaxf(dd[0], dd[1]), fmaxf(dd[2], dd[3]));
        unsigned bmax = __float_as_uint(best);       // dd >= 0: bits order-monotone
        unsigned gm;
        REDUX_MAX_U32(gm, bmax);
        unsigned cand = 0x7FFFFFFFu;                 // my lowest idx matching gm
        if (__float_as_uint(dd[3]) == gm) cand = base + tid + 1536;
        if (__float_as_uint(dd[2]) == gm) cand = base + tid + 1024;
        if (__float_as_uint(dd[1]) == gm) cand = base + tid + 512;
        if (__float_as_uint(dd[0]) == gm) cand = base + tid;
        unsigned wbi;
        REDUX_MIN_U32(wbi, cand);

        if (lane == 0) { swhi[wid] = gm; swbi[wid] = wbi; }
        __syncthreads();

        // ---- CTA-level: redundant in every warp ----
        unsigned hi  = (lane < 16) ? swhi[lane] : 0u;
        unsigned bi2 = (lane < 16) ? swbi[lane] : 0x7FFFFFFFu;
        unsigned gm2;
        REDUX_MAX_U32(gm2, hi);                      // gm2 > 0 always (unselected pts remain)
        unsigned c2 = (hi == gm2) ? bi2 : 0x7FFFFFFFu;
        unsigned cbi;
        REDUX_MIN_U32(cbi, c2);

        // ---- cluster exchange ----
        const int sp = s & 1;
        if (tid == 0) {
            unsigned long long key =
                ((unsigned long long)gm2 << 32) | (unsigned)(8191 - cbi);
            unsigned mySlot = slots_a + (unsigned)((sp * 4 + rank) * 8);
#pragma unroll
            for (unsigned r = 0; r < 4; r++)
                st_arrive_remote(mySlot, mbar_a, key, r);
        }
        MBAR_WAIT_CL(mbar_a, (unsigned)((s - 1) & 1));

        unsigned long long k0 = slots[sp][0], k1 = slots[sp][1];
        unsigned long long k2 = slots[sp][2], k3 = slots[sp][3];
        unsigned long long ka = (k0 > k1) ? k0 : k1;
        unsigned long long kb = (k2 > k3) ? k2 : k3;
        unsigned long long kk = (ka > kb) ? ka : kb;
        const int idx = 8191 - (int)(kk & 0xFFFFFFFFull);

        lx = __ldg(xb + idx);
        ly = __ldg(xb + NN + idx);
        lz = __ldg(xb + 2*NN + idx);

        if (rank == 0 && tid == 0) {
            g_sidx[b * SS + s] = idx;
            out[OFF_IDX + b * SS + s] = (float)idx;
            out[OFF_XYZ + (size_t)(b * 3 + 0) * SS + s] = lx;
            out[OFF_XYZ + (size_t)(b * 3 + 1) * SS + s] = ly;
            out[OFF_XYZ + (size_t)(b * 3 + 2) * SS + s] = lz;
        }
    }

    CLUSTER_SYNC_();          // no CTA exits while peers may still target its smem
}

// ============================================================================
// Kernel 2: gather sampled features  g_sx[b][c][m] = x[b][c][sidx[b][m]]
// ============================================================================
__global__ void gather_kernel(const float* __restrict__ x)
{
    int t = blockIdx.x * blockDim.x + threadIdx.x;
    if (t >= BB * CC * SS) return;
    int m = t & (SS - 1);
    int c = (t >> 11) & 63;
    int b = t >> 17;
    int n = g_sidx[b * SS + m];
    g_sx[t] = x[((size_t)(b * CC + c)) * NN + n];
}

// ============================================================================
// Kernel 3: squared norms of points and queries (sequential channel sum)
// ============================================================================
__global__ void norms_kernel(const float* __restrict__ x)
{
    int t = blockIdx.x * blockDim.x + threadIdx.x;
    if (t < BB * NN) {
        int b = t >> 13, n = t & (NN - 1);
        const float* xb = x + (size_t)(b * CC) * NN + n;
        float acc = 0.0f;
        for (int c = 0; c < CC; c++) {
            float v = xb[(size_t)c * NN];
            acc = __fadd_rn(acc, __fmul_rn(v, v));
        }
        g_pn[t] = acc;
    } else if (t < BB * NN + BB * SS) {
        int t2 = t - BB * NN;
        int b = t2 >> 11, m = t2 & (SS - 1);
        const float* qb = g_sx + (size_t)(b * CC) * SS + m;
        float acc = 0.0f;
        for (int c = 0; c < CC; c++) {
            float v = qb[(size_t)c * SS];
            acc = __fadd_rn(acc, __fmul_rn(v, v));
        }
        g_qn[t2] = acc;
    }
}

// ============================================================================
// Kernel 4: distance GEMM  D[b][m][n] = (qn[m]+pn[n]) - 2*dot(Q[:,m],P[:,n])
// 128x128 tile, K=64, 8x8 register microtile, 256 threads.
// ============================================================================
__global__ __launch_bounds__(256) void knn_gemm_kernel(const float* __restrict__ x)
{
    extern __shared__ float sm[];
    float* Qs = sm;                // [64][128]
    float* Ps = sm + 64 * 128;     // [64][128]

    const int b  = blockIdx.z;
    const int mt = blockIdx.y;
    const int nt = blockIdx.x;
    const int tid = threadIdx.x;

    const float* qb = g_sx + (size_t)(b * CC) * SS + mt * 128;
    const float* pb = x    + (size_t)(b * CC) * NN + nt * 128;

    for (int e = tid; e < 64 * 32; e += 256) {
        int c = e >> 5, i = e & 31;
        ((float4*)(Qs + c * 128))[i] = ((const float4*)(qb + (size_t)c * SS))[i];
        ((float4*)(Ps + c * 128))[i] = ((const float4*)(pb + (size_t)c * NN))[i];
    }
    __syncthreads();

    const int tx = tid & 15, ty = tid >> 4;
    float acc[8][8];
#pragma unroll
    for (int i = 0; i < 8; i++)
#pragma unroll
        for (int j = 0; j < 8; j++) acc[i][j] = 0.0f;

#pragma unroll 8
    for (int j = 0; j < 64; j++) {
        float4 a0 = *(const float4*)(Qs + j * 128 + ty * 8);
        float4 a1 = *(const float4*)(Qs + j * 128 + ty * 8 + 4);
        float4 c0 = *(const float4*)(Ps + j * 128 + tx * 8);
        float4 c1 = *(const float4*)(Ps + j * 128 + tx * 8 + 4);
        float av[8] = {a0.x, a0.y, a0.z, a0.w, a1.x, a1.y, a1.z, a1.w};
        float bv[8] = {c0.x, c0.y, c0.z, c0.w, c1.x, c1.y, c1.z, c1.w};
#pragma unroll
        for (int i = 0; i < 8; i++)
#pragma unroll
            for (int jj = 0; jj < 8; jj++)
                acc[i][jj] = fmaf(av[i], bv[jj], acc[i][jj]);
    }

    const int m0 = mt * 128 + ty * 8;
    const int n0 = nt * 128 + tx * 8;
    float qnv[8], pnv[8];
#pragma unroll
    for (int i = 0; i < 8; i++) qnv[i] = g_qn[b * SS + m0 + i];
#pragma unroll
    for (int j = 0; j < 8; j++) pnv[j] = g_pn[b * NN + n0 + j];

#pragma unroll
    for (int i = 0; i < 8; i++) {
        float* Drow = g_D + ((size_t)(b * SS + m0 + i)) * NN + n0;
        float4 v0, v1;
        float t0 = __fadd_rn(qnv[i], pnv[0]); v0.x = t0 - 2.0f * acc[i][0];
        float t1 = __fadd_rn(qnv[i], pnv[1]); v0.y = t1 - 2.0f * acc[i][1];
        float t2 = __fadd_rn(qnv[i], pnv[2]); v0.z = t2 - 2.0f * acc[i][2];
        float t3 = __fadd_rn(qnv[i], pnv[3]); v0.w = t3 - 2.0f * acc[i][3];
        float t4 = __fadd_rn(qnv[i], pnv[4]); v1.x = t4 - 2.0f * acc[i][4];
        float t5 = __fadd_rn(qnv[i], pnv[5]); v1.y = t5 - 2.0f * acc[i][5];
        float t6 = __fadd_rn(qnv[i], pnv[6]); v1.z = t6 - 2.0f * acc[i][6];
        float t7 = __fadd_rn(qnv[i], pnv[7]); v1.w = t7 - 2.0f * acc[i][7];
        ((float4*)Drow)[0] = v0;
        ((float4*)Drow)[1] = v1;
    }
}

// ============================================================================
// Kernel 5: per-row top-17 smallest (lowest-index tie-break), drop the
// nearest (self), write indices 1..16. One warp per row.
// ============================================================================
__global__ __launch_bounds__(256) void topk_kernel()
{
    __shared__ unsigned long long cand[8][544];
    const int w    = threadIdx.x >> 5;
    const int lane = threadIdx.x & 31;
    const int row  = blockIdx.x * 8 + w;     // 0 .. BB*SS-1

    const float* dr = g_D + (size_t)row * NN;

    unsigned long long L[17];
#pragma unroll
    for (int i = 0; i < 17; i++) L[i] = ~0ULL;

    for (int t = 0; t < NN / 32; t++) {
        const int n = lane + (t << 5);
        float f = dr[n];
        unsigned fb = __float_as_uint(f);
        fb = (fb & 0x80000000u) ? ~fb : (fb | 0x80000000u);   // order-preserving map
        unsigned long long key = ((unsigned long long)fb << 32) | (unsigned)n;
        if (key < L[16]) {
            L[16] = key;
#pragma unroll
            for (int i = 16; i > 0; i--) {
                unsigned long long lo = (L[i - 1] < L[i]) ? L[i - 1] : L[i];
                unsigned long long hi = (L[i - 1] < L[i]) ? L[i] : L[i - 1];
                L[i - 1] = lo; L[i] = hi;
            }
        }
    }
#pragma unroll
    for (int i = 0; i < 17; i++) cand[w][lane * 17 + i] = L[i];
    __syncwarp();

    for (int r = 0; r < 17; r++) {
        unsigned long long mk = ~0ULL;
        int ms = 0;
#pragma unroll
        for (int q = 0; q < 17; q++) {
            unsigned long long v = cand[w][lane + (q << 5)];
            if (v < mk) { mk = v; ms = lane + (q << 5); }
        }
        unsigned long long gk = mk;
#pragma unroll
        for (int off = 16; off; off >>= 1) {
            unsigned long long o = __shfl_xor_sync(0xFFFFFFFFu, gk, off);
            if (o < gk) gk = o;
        }
        if (gk == mk) cand[w][ms] = ~0ULL;       // keys unique -> single owner
        if (r > 0 && lane == 0)
            g_knn[row * KNBR + r - 1] = (int)(gk & (unsigned long long)(NN - 1));
        __syncwarp();
    }
}

// ============================================================================
// Kernel 6: fused EdgeConv + max-pool. 16 samples per block, 256 threads.
// Center-dependent conv halves are k-invariant (precomputed per sample).
// ============================================================================
__device__ __forceinline__ void load_wt(const float* __restrict__ W, int RL, int CO,
                                        float* __restrict__ dst, int tid)
{
    for (int e = tid; e < 4096; e += 256) {
        int j = e >> 6, o = e & 63;
        dst[j * 64 + o] = W[o * RL + CO + j];
    }
}

__device__ __forceinline__ void compute_u(const float* __restrict__ W, int RL, int CO,
                                          const float* __restrict__ bias,
                                          const float* __restrict__ sC,
                                          float* __restrict__ sU, int tid)
{
    const int o = tid & 63, g = tid >> 6;     // 4 ml per thread
    float a[4] = {0.f, 0.f, 0.f, 0.f};
    for (int j = 0; j < 64; j++) {
        float w = W[o * RL + CO + j];
#pragma unroll
        for (int i = 0; i < 4; i++)
            a[i] = fmaf(w, sC[j * 16 + g * 4 + i], a[i]);
    }
    float bv = bias[o];
#pragma unroll
    for (int i = 0; i < 4; i++) sU[o * 16 + g * 4 + i] = a[i] + bv;
}

__device__ __forceinline__ void gemm_stage(const float* __restrict__ sWt,
                                           const float* __restrict__ sIn,
                                           const float* __restrict__ sU,
                                           float* __restrict__ sOut, int tid)
{
    const int tx = tid & 31, ty = tid >> 5;
    const int col0 = tx * 8, o0 = ty * 8;
    float acc[8][8];
#pragma unroll
    for (int i = 0; i < 8; i++)
#pragma unroll
        for (int j = 0; j < 8; j++) acc[i][j] = 0.0f;

#pragma unroll 4
    for (int j = 0; j < 64; j++) {
        float4 w0 = *(const float4*)(sWt + j * 64 + o0);
        float4 w1 = *(const float4*)(sWt + j * 64 + o0 + 4);
        float4 e0 = *(const float4*)(sIn + j * 256 + col0);
        float4 e1 = *(const float4*)(sIn + j * 256 + col0 + 4);
        float wv[8] = {w0.x, w0.y, w0.z, w0.w, w1.x, w1.y, w1.z, w1.w};
        float ev[8] = {e0.x, e0.y, e0.z, e0.w, e1.x, e1.y, e1.z, e1.w};
#pragma unroll
        for (int i = 0; i < 8; i++)
#pragma unroll
            for (int jj = 0; jj < 8; jj++)
                acc[i][jj] = fmaf(wv[i], ev[jj], acc[i][jj]);
    }
    const int ml = tx >> 1;
#pragma unroll
    for (int i = 0; i < 8; i++) {
        float u = sU[(o0 + i) * 16 + ml];
#pragma unroll
        for (int jj = 0; jj < 8; jj++) {
            float v = acc[i][jj] + u;
            sOut[(o0 + i) * 256 + col0 + jj] = fmaxf(v, 0.0f);
        }
    }
}

__global__ __launch_bounds__(256) void edge_kernel(
    const float* __restrict__ x,
    const float* __restrict__ W0, const float* __restrict__ b0,
    const float* __restrict__ W1, const float* __restrict__ b1,
    const float* __restrict__ W2, const float* __restrict__ b2,
    float* __restrict__ out)
{
    extern __shared__ float sm[];
    float* sE  = sm;                  // [64][256]  -> later reused as H1
    float* sH0 = sE  + 64 * 256;      // [64][256]
    float* sWa = sH0 + 64 * 256;      // [64][64]  transposed weight
    float* sWb = sWa + 64 * 64;       // [64][64]
    float* sC  = sWb + 64 * 64;       // [64][16]
    float* sU  = sC  + 64 * 16;       // [64][16]

    const int blk = blockIdx.x;
    const int b   = blk >> 7;
    const int m0  = (blk & 127) * 16;
    const int tid = threadIdx.x;

    // centers
    for (int e = tid; e < 1024; e += 256) {
        int c = e >> 4, ml = e & 15;
        sC[e] = g_sx[((size_t)(b * CC + c)) * SS + m0 + ml];
    }
    __syncthreads();

    // E = knn_feat - center (one column per thread), plus stage-0 weights/U
    {
        const int col = tid;
        const int ml = col >> 4, kk = col & 15;
        const int n = g_knn[(b * SS + m0 + ml) * KNBR + kk];
        const float* xb = x + (size_t)(b * CC) * NN + n;
#pragma unroll 8
        for (int c = 0; c < CC; c++)
            sE[c * 256 + col] = xb[(size_t)c * NN] - sC[c * 16 + ml];
    }
    load_wt(W0, 128, 64, sWa, tid);                 // W0b^T (diff part)
    compute_u(W0, 128, 0, b0, sC, sU, tid);         // U0 = W0a@C + b0
    __syncthreads();

    gemm_stage(sWa, sE, sU, sH0, tid);              // H0 = relu(...)
    __syncthreads();

    load_wt(W1, 128, 0, sWa, tid);                  // W1a^T (h0 part)
    compute_u(W1, 128, 64, b1, sC, sU, tid);        // V1 = W1b@C + b1
    __syncthreads();

    gemm_stage(sWa, sH0, sU, sE, tid);              // H1 -> reuse sE buffer
    __syncthreads();
    float* sH1 = sE;

    load_wt(W2, 192, 0,  sWa, tid);                 // W2a^T (h1 part)
    load_wt(W2, 192, 64, sWb, tid);                 // W2b^T (h0 part)
    compute_u(W2, 192, 128, b2, sC, sU, tid);       // V2 = W2c@C + b2
    __syncthreads();

    // stage 2: h2 = W2a@H1 + W2b@H0 + V2  (no relu), max over k
    {
        const int tx = tid & 31, ty = tid >> 5;
        const int col0 = tx * 8, o0 = ty * 8;
        float acc[8][8];
#pragma unroll
        for (int i = 0; i < 8; i++)
#pragma unroll
            for (int j = 0; j < 8; j++) acc[i][j] = 0.0f;

#pragma unroll 2
        for (int j = 0; j < 64; j++) {
            float4 w0 = *(const float4*)(sWa + j * 64 + o0);
            float4 w1 = *(const float4*)(sWa + j * 64 + o0 + 4);
            float4 u0 = *(const float4*)(sWb + j * 64 + o0);
            float4 u1 = *(const float4*)(sWb + j * 64 + o0 + 4);
            float4 h1a = *(const float4*)(sH1 + j * 256 + col0);
            float4 h1b = *(const float4*)(sH1 + j * 256 + col0 + 4);
            float4 h0a = *(const float4*)(sH0 + j * 256 + col0);
            float4 h0b = *(const float4*)(sH0 + j * 256 + col0 + 4);
            float wv[8]  = {w0.x, w0.y, w0.z, w0.w, w1.x, w1.y, w1.z, w1.w};
            float w2v[8] = {u0.x, u0.y, u0.z, u0.w, u1.x, u1.y, u1.z, u1.w};
            float v1v[8] = {h1a.x, h1a.y, h1a.z, h1a.w, h1b.x, h1b.y, h1b.z, h1b.w};
            float v0v[8] = {h0a.x, h0a.y, h0a.z, h0a.w, h0b.x, h0b.y, h0b.z, h0b.w};
#pragma unroll
            for (int i = 0; i < 8; i++)
#pragma unroll
                for (int jj = 0; jj < 8; jj++) {
                    acc[i][jj] = fmaf(wv[i],  v1v[jj], acc[i][jj]);
                    acc[i][jj] = fmaf(w2v[i], v0v[jj], acc[i][jj]);
                }
        }
        const int ml = tx >> 1;
#pragma unroll
        for (int i = 0; i < 8; i++) {
            float mx = acc[i][0];
#pragma unroll
            for (int jj = 1; jj < 8; jj++) mx = fmaxf(mx, acc[i][jj]);
            mx = mx + sU[(o0 + i) * 16 + ml];
            float other = __shfl_xor_sync(0xFFFFFFFFu, mx, 1);
            mx = fmaxf(mx, other);
            if ((tx & 1) == 0)
                out[(size_t)(b * 256 + o0 + i) * SS + m0 + ml] = mx;   // ch 0..63
        }
    }

    // h1 / h0 maxes and center channels
    for (int e = tid; e < 1024; e += 256) {
        int ch = e >> 4, ml = e & 15;
        float mx0 = -__int_as_float(0x7F7FFFFF);
        float mx1 = mx0;
#pragma unroll
        for (int kk = 0; kk < 16; kk++) {
            mx0 = fmaxf(mx0, sH0[ch * 256 + ml * 16 + kk]);
            mx1 = fmaxf(mx1, sH1[ch * 256 + ml * 16 + kk]);
        }
        size_t base = (size_t)b * 256;
        out[(base + 64  + ch) * SS + m0 + ml] = mx1;            // ch 64..127
        out[(base + 128 + ch) * SS + m0 + ml] = mx0;            // ch 128..191
        out[(base + 192 + ch) * SS + m0 + ml] = sC[ch * 16 + ml]; // ch 192..255
    }
}

// ============================================================================
extern "C" void kernel_launch(void* const* d_in, const int* in_sizes, int n_in,
                              void* d_out, int out_size)
{
    const float* x   = (const float*)d_in[0];
    const float* xyz = (const float*)d_in[1];
    const float* W0  = (const float*)d_in[2];
    const float* b0  = (const float*)d_in[3];
    const float* W1  = (const float*)d_in[4];
    const float* b1  = (const float*)d_in[5];
    const float* W2  = (const float*)d_in[6];
    const float* b2  = (const float*)d_in[7];
    float* out = (float*)d_out;

    cudaFuncSetAttribute(knn_gemm_kernel,
                         cudaFuncAttributeMaxDynamicSharedMemorySize, 65536);
    cudaFuncSetAttribute(edge_kernel,
                         cudaFuncAttributeMaxDynamicSharedMemorySize, 172032);

    // 16 CTAs = 4 batches x 4-CTA clusters
    fps_kernel<<<BB * 4, 512>>>(xyz, out);
    gather_kernel<<<(BB * CC * SS + 255) / 256, 256>>>(x);
    norms_kernel<<<(BB * NN + BB * SS + 255) / 256, 256>>>(x);
    knn_gemm_kernel<<<dim3(NN / 128, SS / 128, BB), 256, 65536>>>(x);
    topk_kernel<<<BB * SS / 8, 256>>>();
    edge_kernel<<<BB * SS / 16, 256, 172032>>>(x, W0, b0, W1, b1, W2, b2, out);
}

// round 7
// speedup vs baseline: 2.2112x; 2.2112x over previous
#include <cuda_runtime.h>

#define BB 4
#define CC 64
#define NN 8192
#define SS 2048
#define KNBR 16
#define GG 64

#define OFF_XYZ (4*256*2048)            /* 2097152 */
#define OFF_IDX (OFF_XYZ + 4*3*2048)    /* 2121728 */

#define MUL_F32X2(out, a, b) \
    asm("mul.rn.f32x2 %0, %1, %2;" : "=l"(out) : "l"(a), "l"(b))
#define ADD_F32X2(out, a, b) \
    asm("add.rn.f32x2 %0, %1, %2;" : "=l"(out) : "l"(a), "l"(b))
#define SUB_F32X2(out, a, b) \
    asm("sub.rn.f32x2 %0, %1, %2;" : "=l"(out) : "l"(a), "l"(b))
#define PACK_F32X2(out, lo, hi) \
    asm("mov.b64 %0, {%1, %2};" : "=l"(out) : "f"(lo), "f"(hi))
#define UNPACK_F32X2(lo, hi, in) \
    asm("mov.b64 {%0, %1}, %2;" : "=f"(lo), "=f"(hi) : "l"(in))
#define REDUX_MAX_U32(d, s) \
    asm volatile("redux.sync.max.u32 %0, %1, 0xffffffff;" : "=r"(d) : "r"(s))

// ---------------- scratch (static device globals; no allocations) ----------
__device__ int   g_sidx[BB*SS];
__device__ float g_sx[BB*CC*SS];
__device__ float g_pn[BB*NN];
__device__ float g_qn[BB*SS];
__device__ float g_D[(size_t)BB*SS*NN];    // 256 MB distance matrix
__device__ int   g_knn[BB*SS*KNBR];

// ============================================================================
// Kernel 1: Farthest point sampling. One block per batch, 512 threads,
// 16 points/thread (8 packed f32x2 pairs). Bit-exact vs reference: no fma
// contraction, ((dx^2+dy^2)+dz^2) association, fminf accumulation, argmax
// with lowest-index tie-break (deferred rescan + atomicMin).
// Center broadcast via a packed float4 table in 128KB dynamic smem (single
// LDS.128 per thread instead of 3 LDG per thread per iteration).
// ============================================================================
__global__ __launch_bounds__(512) void fps_kernel(const float* __restrict__ xyz,
                                                  float* __restrict__ out)
{
    extern __shared__ float4 spk[];               // [8192] packed {x,y,z,0}

    const int b    = blockIdx.x;
    const int tid  = threadIdx.x;
    const int lane = tid & 31;
    const int wid  = tid >> 5;
    const float* xb = xyz + (size_t)b * 3 * NN;

    __shared__ unsigned swmax[16];
    __shared__ int      sh_idx[2];

    // prologue: pack coords into smem table (one-time)
#pragma unroll
    for (int k = 0; k < 16; k++) {
        int i = tid + 512 * k;
        float4 v;
        v.x = xb[i];
        v.y = xb[NN + i];
        v.z = xb[2*NN + i];
        v.w = 0.0f;
        spk[i] = v;
    }

    // 16 points per thread, packed in pairs: pair jp holds points
    // n0 = tid + 1024*jp  and  n1 = tid + 1024*jp + 512
    unsigned long long pxp[8], pyp[8], pzp[8];
    float dd[16];
    const float FMAX = __int_as_float(0x7F7FFFFF);
#pragma unroll
    for (int jp = 0; jp < 8; jp++) {
        int n0 = tid + 1024 * jp;
        int n1 = n0 + 512;
        PACK_F32X2(pxp[jp], xb[n0],          xb[n1]);
        PACK_F32X2(pyp[jp], xb[NN + n0],     xb[NN + n1]);
        PACK_F32X2(pzp[jp], xb[2*NN + n0],   xb[2*NN + n1]);
        dd[2*jp]     = FMAX;
        dd[2*jp + 1] = FMAX;
    }

    if (tid == 0) {
        sh_idx[0] = 0x7FFFFFFF;
        sh_idx[1] = 0x7FFFFFFF;
        g_sidx[b * SS + 0] = 0;
        out[OFF_IDX + b * SS + 0] = 0.0f;
        out[OFF_XYZ + (size_t)(b * 3 + 0) * SS + 0] = xb[0];
        out[OFF_XYZ + (size_t)(b * 3 + 1) * SS + 0] = xb[NN];
        out[OFF_XYZ + (size_t)(b * 3 + 2) * SS + 0] = xb[2*NN];
    }
    __syncthreads();

    float4 ce = spk[0];       // current center (same value in every thread)

    for (int s = 1; s < SS; s++) {
        unsigned long long cx2, cy2, cz2;
        PACK_F32X2(cx2, ce.x, ce.x);
        PACK_F32X2(cy2, ce.y, ce.y);
        PACK_F32X2(cz2, ce.z, ce.z);

        float best = 0.0f;   // dists are >= 0
#pragma unroll
        for (int jp = 0; jp < 8; jp++) {
            unsigned long long dx2, dy2, dz2, sx2, sy2, sz2, s12, s22;
            SUB_F32X2(dx2, pxp[jp], cx2);       // px - cx (exact rn)
            SUB_F32X2(dy2, pyp[jp], cy2);
            SUB_F32X2(dz2, pzp[jp], cz2);
            MUL_F32X2(sx2, dx2, dx2);
            MUL_F32X2(sy2, dy2, dy2);
            MUL_F32X2(sz2, dz2, dz2);
            ADD_F32X2(s12, sx2, sy2);           // (dx^2 + dy^2)
            ADD_F32X2(s22, s12, sz2);           // + dz^2
            float t0, t1;
            UNPACK_F32X2(t0, t1, s22);
            float n0 = fminf(dd[2*jp],     t0);
            float n1 = fminf(dd[2*jp + 1], t1);
            dd[2*jp]     = n0;
            dd[2*jp + 1] = n1;
            best = fmaxf(best, n0);
            best = fmaxf(best, n1);
        }

        // per-warp max of nonneg float bits (order-monotone)
        unsigned bmax = __float_as_uint(best);
        unsigned wm;
        REDUX_MAX_U32(wm, bmax);
        if (lane == 0) swmax[wid] = wm;
        __syncthreads();                                    // barrier (a)

        // tid 0 resets the OTHER parity slot (used 2 iters out)
        if (tid == 0) sh_idx[(s + 1) & 1] = 0x7FFFFFFF;

        // every warp redundantly reduces the 16 warp maxima
        unsigned v = swmax[lane & 15];
        unsigned gmax;
        REDUX_MAX_U32(gmax, v);

        // candidate threads rescan register dists for lowest matching index
        if (bmax == gmax) {
            int cand = 0x7FFFFFFF;
#pragma unroll
            for (int j = 15; j >= 0; j--)
                if (__float_as_uint(dd[j]) == gmax) cand = tid + 512 * j;
            atomicMin(&sh_idx[s & 1], cand);
        }
        __syncthreads();                                    // barrier (b)

        const int idx = sh_idx[s & 1];
        ce = spk[idx];                       // single broadcast LDS.128

        if (tid == 0) {
            g_sidx[b * SS + s] = idx;
            out[OFF_IDX + b * SS + s] = (float)idx;
            out[OFF_XYZ + (size_t)(b * 3 + 0) * SS + s] = ce.x;
            out[OFF_XYZ + (size_t)(b * 3 + 1) * SS + s] = ce.y;
            out[OFF_XYZ + (size_t)(b * 3 + 2) * SS + s] = ce.z;
        }
    }
}

// ============================================================================
// Kernel 2: gather sampled features  g_sx[b][c][m] = x[b][c][sidx[b][m]]
// ============================================================================
__global__ void gather_kernel(const float* __restrict__ x)
{
    int t = blockIdx.x * blockDim.x + threadIdx.x;
    if (t >= BB * CC * SS) return;
    int m = t & (SS - 1);
    int c = (t >> 11) & 63;
    int b = t >> 17;
    int n = g_sidx[b * SS + m];
    g_sx[t] = x[((size_t)(b * CC + c)) * NN + n];
}

// ============================================================================
// Kernel 3: squared norms of points and queries (sequential channel sum)
// ============================================================================
__global__ void norms_kernel(const float* __restrict__ x)
{
    int t = blockIdx.x * blockDim.x + threadIdx.x;
    if (t < BB * NN) {
        int b = t >> 13, n = t & (NN - 1);
        const float* xb = x + (size_t)(b * CC) * NN + n;
        float acc = 0.0f;
        for (int c = 0; c < CC; c++) {
            float v = xb[(size_t)c * NN];
            acc = __fadd_rn(acc, __fmul_rn(v, v));
        }
        g_pn[t] = acc;
    } else if (t < BB * NN + BB * SS) {
        int t2 = t - BB * NN;
        int b = t2 >> 11, m = t2 & (SS - 1);
        const float* qb = g_sx + (size_t)(b * CC) * SS + m;
        float acc = 0.0f;
        for (int c = 0; c < CC; c++) {
            float v = qb[(size_t)c * SS];
            acc = __fadd_rn(acc, __fmul_rn(v, v));
        }
        g_qn[t2] = acc;
    }
}

// ============================================================================
// Kernel 4: distance GEMM  D[b][m][n] = (qn[m]+pn[n]) - 2*dot(Q[:,m],P[:,n])
// 128x128 tile, K=64, 8x8 register microtile, 256 threads.
// ============================================================================
__global__ __launch_bounds__(256) void knn_gemm_kernel(const float* __restrict__ x)
{
    extern __shared__ float sm[];
    float* Qs = sm;                // [64][128]
    float* Ps = sm + 64 * 128;     // [64][128]

    const int b  = blockIdx.z;
    const int mt = blockIdx.y;
    const int nt = blockIdx.x;
    const int tid = threadIdx.x;

    const float* qb = g_sx + (size_t)(b * CC) * SS + mt * 128;
    const float* pb = x    + (size_t)(b * CC) * NN + nt * 128;

    for (int e = tid; e < 64 * 32; e += 256) {
        int c = e >> 5, i = e & 31;
        ((float4*)(Qs + c * 128))[i] = ((const float4*)(qb + (size_t)c * SS))[i];
        ((float4*)(Ps + c * 128))[i] = ((const float4*)(pb + (size_t)c * NN))[i];
    }
    __syncthreads();

    const int tx = tid & 15, ty = tid >> 4;
    float acc[8][8];
#pragma unroll
    for (int i = 0; i < 8; i++)
#pragma unroll
        for (int j = 0; j < 8; j++) acc[i][j] = 0.0f;

#pragma unroll 8
    for (int j = 0; j < 64; j++) {
        float4 a0 = *(const float4*)(Qs + j * 128 + ty * 8);
        float4 a1 = *(const float4*)(Qs + j * 128 + ty * 8 + 4);
        float4 c0 = *(const float4*)(Ps + j * 128 + tx * 8);
        float4 c1 = *(const float4*)(Ps + j * 128 + tx * 8 + 4);
        float av[8] = {a0.x, a0.y, a0.z, a0.w, a1.x, a1.y, a1.z, a1.w};
        float bv[8] = {c0.x, c0.y, c0.z, c0.w, c1.x, c1.y, c1.z, c1.w};
#pragma unroll
        for (int i = 0; i < 8; i++)
#pragma unroll
            for (int jj = 0; jj < 8; jj++)
                acc[i][jj] = fmaf(av[i], bv[jj], acc[i][jj]);
    }

    const int m0 = mt * 128 + ty * 8;
    const int n0 = nt * 128 + tx * 8;
    float qnv[8], pnv[8];
#pragma unroll
    for (int i = 0; i < 8; i++) qnv[i] = g_qn[b * SS + m0 + i];
#pragma unroll
    for (int j = 0; j < 8; j++) pnv[j] = g_pn[b * NN + n0 + j];

#pragma unroll
    for (int i = 0; i < 8; i++) {
        float* Drow = g_D + ((size_t)(b * SS + m0 + i)) * NN + n0;
        float4 v0, v1;
        float t0 = __fadd_rn(qnv[i], pnv[0]); v0.x = t0 - 2.0f * acc[i][0];
        float t1 = __fadd_rn(qnv[i], pnv[1]); v0.y = t1 - 2.0f * acc[i][1];
        float t2 = __fadd_rn(qnv[i], pnv[2]); v0.z = t2 - 2.0f * acc[i][2];
        float t3 = __fadd_rn(qnv[i], pnv[3]); v0.w = t3 - 2.0f * acc[i][3];
        float t4 = __fadd_rn(qnv[i], pnv[4]); v1.x = t4 - 2.0f * acc[i][4];
        float t5 = __fadd_rn(qnv[i], pnv[5]); v1.y = t5 - 2.0f * acc[i][5];
        float t6 = __fadd_rn(qnv[i], pnv[6]); v1.z = t6 - 2.0f * acc[i][6];
        float t7 = __fadd_rn(qnv[i], pnv[7]); v1.w = t7 - 2.0f * acc[i][7];
        ((float4*)Drow)[0] = v0;
        ((float4*)Drow)[1] = v1;
    }
}

// ============================================================================
// Kernel 5: per-row top-17 smallest (lowest-index tie-break), drop the
// nearest (self), write indices 1..16. One warp per row.
// ============================================================================
__global__ __launch_bounds__(256) void topk_kernel()
{
    __shared__ unsigned long long cand[8][544];
    const int w    = threadIdx.x >> 5;
    const int lane = threadIdx.x & 31;
    const int row  = blockIdx.x * 8 + w;     // 0 .. BB*SS-1

    const float* dr = g_D + (size_t)row * NN;

    unsigned long long L[17];
#pragma unroll
    for (int i = 0; i < 17; i++) L[i] = ~0ULL;

    for (int t = 0; t < NN / 32; t++) {
        const int n = lane + (t << 5);
        float f = dr[n];
        unsigned fb = __float_as_uint(f);
        fb = (fb & 0x80000000u) ? ~fb : (fb | 0x80000000u);   // order-preserving map
        unsigned long long key = ((unsigned long long)fb << 32) | (unsigned)n;
        if (key < L[16]) {
            L[16] = key;
#pragma unroll
            for (int i = 16; i > 0; i--) {
                unsigned long long lo = (L[i - 1] < L[i]) ? L[i - 1] : L[i];
                unsigned long long hi = (L[i - 1] < L[i]) ? L[i] : L[i - 1];
                L[i - 1] = lo; L[i] = hi;
            }
        }
    }
#pragma unroll
    for (int i = 0; i < 17; i++) cand[w][lane * 17 + i] = L[i];
    __syncwarp();

    for (int r = 0; r < 17; r++) {
        unsigned long long mk = ~0ULL;
        int ms = 0;
#pragma unroll
        for (int q = 0; q < 17; q++) {
            unsigned long long v = cand[w][lane + (q << 5)];
            if (v < mk) { mk = v; ms = lane + (q << 5); }
        }
        unsigned long long gk = mk;
#pragma unroll
        for (int off = 16; off; off >>= 1) {
            unsigned long long o = __shfl_xor_sync(0xFFFFFFFFu, gk, off);
            if (o < gk) gk = o;
        }
        if (gk == mk) cand[w][ms] = ~0ULL;       // keys unique -> single owner
        if (r > 0 && lane == 0)
            g_knn[row * KNBR + r - 1] = (int)(gk & (unsigned long long)(NN - 1));
        __syncwarp();
    }
}

// ============================================================================
// Kernel 6: fused EdgeConv + max-pool. 16 samples per block, 256 threads.
// Center-dependent conv halves are k-invariant (precomputed per sample).
// ============================================================================
__device__ __forceinline__ void load_wt(const float* __restrict__ W, int RL, int CO,
                                        float* __restrict__ dst, int tid)
{
    for (int e = tid; e < 4096; e += 256) {
        int j = e >> 6, o = e & 63;
        dst[j * 64 + o] = W[o * RL + CO + j];
    }
}

__device__ __forceinline__ void compute_u(const float* __restrict__ W, int RL, int CO,
                                          const float* __restrict__ bias,
                                          const float* __restrict__ sC,
                                          float* __restrict__ sU, int tid)
{
    const int o = tid & 63, g = tid >> 6;     // 4 ml per thread
    float a[4] = {0.f, 0.f, 0.f, 0.f};
    for (int j = 0; j < 64; j++) {
        float w = W[o * RL + CO + j];
#pragma unroll
        for (int i = 0; i < 4; i++)
            a[i] = fmaf(w, sC[j * 16 + g * 4 + i], a[i]);
    }
    float bv = bias[o];
#pragma unroll
    for (int i = 0; i < 4; i++) sU[o * 16 + g * 4 + i] = a[i] + bv;
}

__device__ __forceinline__ void gemm_stage(const float* __restrict__ sWt,
                                           const float* __restrict__ sIn,
                                           const float* __restrict__ sU,
                                           float* __restrict__ sOut, int tid)
{
    const int tx = tid & 31, ty = tid >> 5;
    const int col0 = tx * 8, o0 = ty * 8;
    float acc[8][8];
#pragma unroll
    for (int i = 0; i < 8; i++)
#pragma unroll
        for (int j = 0; j < 8; j++) acc[i][j] = 0.0f;

#pragma unroll 4
    for (int j = 0; j < 64; j++) {
        float4 w0 = *(const float4*)(sWt + j * 64 + o0);
        float4 w1 = *(const float4*)(sWt + j * 64 + o0 + 4);
        float4 e0 = *(const float4*)(sIn + j * 256 + col0);
        float4 e1 = *(const float4*)(sIn + j * 256 + col0 + 4);
        float wv[8] = {w0.x, w0.y, w0.z, w0.w, w1.x, w1.y, w1.z, w1.w};
        float ev[8] = {e0.x, e0.y, e0.z, e0.w, e1.x, e1.y, e1.z, e1.w};
#pragma unroll
        for (int i = 0; i < 8; i++)
#pragma unroll
            for (int jj = 0; jj < 8; jj++)
                acc[i][jj] = fmaf(wv[i], ev[jj], acc[i][jj]);
    }
    const int ml = tx >> 1;
#pragma unroll
    for (int i = 0; i < 8; i++) {
        float u = sU[(o0 + i) * 16 + ml];
#pragma unroll
        for (int jj = 0; jj < 8; jj++) {
            float v = acc[i][jj] + u;
            sOut[(o0 + i) * 256 + col0 + jj] = fmaxf(v, 0.0f);
        }
    }
}

__global__ __launch_bounds__(256) void edge_kernel(
    const float* __restrict__ x,
    const float* __restrict__ W0, const float* __restrict__ b0,
    const float* __restrict__ W1, const float* __restrict__ b1,
    const float* __restrict__ W2, const float* __restrict__ b2,
    float* __restrict__ out)
{
    extern __shared__ float sm[];
    float* sE  = sm;                  // [64][256]  -> later reused as H1
    float* sH0 = sE  + 64 * 256;      // [64][256]
    float* sWa = sH0 + 64 * 256;      // [64][64]  transposed weight
    float* sWb = sWa + 64 * 64;       // [64][64]
    float* sC  = sWb + 64 * 64;       // [64][16]
    float* sU  = sC  + 64 * 16;       // [64][16]

    const int blk = blockIdx.x;
    const int b   = blk >> 7;
    const int m0  = (blk & 127) * 16;
    const int tid = threadIdx.x;

    // centers
    for (int e = tid; e < 1024; e += 256) {
        int c = e >> 4, ml = e & 15;
        sC[e] = g_sx[((size_t)(b * CC + c)) * SS + m0 + ml];
    }
    __syncthreads();

    // E = knn_feat - center (one column per thread), plus stage-0 weights/U
    {
        const int col = tid;
        const int ml = col >> 4, kk = col & 15;
        const int n = g_knn[(b * SS + m0 + ml) * KNBR + kk];
        const float* xb = x + (size_t)(b * CC) * NN + n;
#pragma unroll 8
        for (int c = 0; c < CC; c++)
            sE[c * 256 + col] = xb[(size_t)c * NN] - sC[c * 16 + ml];
    }
    load_wt(W0, 128, 64, sWa, tid);                 // W0b^T (diff part)
    compute_u(W0, 128, 0, b0, sC, sU, tid);         // U0 = W0a@C + b0
    __syncthreads();

    gemm_stage(sWa, sE, sU, sH0, tid);              // H0 = relu(...)
    __syncthreads();

    load_wt(W1, 128, 0, sWa, tid);                  // W1a^T (h0 part)
    compute_u(W1, 128, 64, b1, sC, sU, tid);        // V1 = W1b@C + b1
    __syncthreads();

    gemm_stage(sWa, sH0, sU, sE, tid);              // H1 -> reuse sE buffer
    __syncthreads();
    float* sH1 = sE;

    load_wt(W2, 192, 0,  sWa, tid);                 // W2a^T (h1 part)
    load_wt(W2, 192, 64, sWb, tid);                 // W2b^T (h0 part)
    compute_u(W2, 192, 128, b2, sC, sU, tid);       // V2 = W2c@C + b2
    __syncthreads();

    // stage 2: h2 = W2a@H1 + W2b@H0 + V2  (no relu), max over k
    {
        const int tx = tid & 31, ty = tid >> 5;
        const int col0 = tx * 8, o0 = ty * 8;
        float acc[8][8];
#pragma unroll
        for (int i = 0; i < 8; i++)
#pragma unroll
            for (int j = 0; j < 8; j++) acc[i][j] = 0.0f;

#pragma unroll 2
        for (int j = 0; j < 64; j++) {
            float4 w0 = *(const float4*)(sWa + j * 64 + o0);
            float4 w1 = *(const float4*)(sWa + j * 64 + o0 + 4);
            float4 u0 = *(const float4*)(sWb + j * 64 + o0);
            float4 u1 = *(const float4*)(sWb + j * 64 + o0 + 4);
            float4 h1a = *(const float4*)(sH1 + j * 256 + col0);
            float4 h1b = *(const float4*)(sH1 + j * 256 + col0 + 4);
            float4 h0a = *(const float4*)(sH0 + j * 256 + col0);
            float4 h0b = *(const float4*)(sH0 + j * 256 + col0 + 4);
            float wv[8]  = {w0.x, w0.y, w0.z, w0.w, w1.x, w1.y, w1.z, w1.w};
            float w2v[8] = {u0.x, u0.y, u0.z, u0.w, u1.x, u1.y, u1.z, u1.w};
            float v1v[8] = {h1a.x, h1a.y, h1a.z, h1a.w, h1b.x, h1b.y, h1b.z, h1b.w};
            float v0v[8] = {h0a.x, h0a.y, h0a.z, h0a.w, h0b.x, h0b.y, h0b.z, h0b.w};
#pragma unroll
            for (int i = 0; i < 8; i++)
#pragma unroll
                for (int jj = 0; jj < 8; jj++) {
                    acc[i][jj] = fmaf(wv[i],  v1v[jj], acc[i][jj]);
                    acc[i][jj] = fmaf(w2v[i], v0v[jj], acc[i][jj]);
                }
        }
        const int ml = tx >> 1;
#pragma unroll
        for (int i = 0; i < 8; i++) {
            float mx = acc[i][0];
#pragma unroll
            for (int jj = 1; jj < 8; jj++) mx = fmaxf(mx, acc[i][jj]);
            mx = mx + sU[(o0 + i) * 16 + ml];
            float other = __shfl_xor_sync(0xFFFFFFFFu, mx, 1);
            mx = fmaxf(mx, other);
            if ((tx & 1) == 0)
                out[(size_t)(b * 256 + o0 + i) * SS + m0 + ml] = mx;   // ch 0..63
        }
    }

    // h1 / h0 maxes and center channels
    for (int e = tid; e < 1024; e += 256) {
        int ch = e >> 4, ml = e & 15;
        float mx0 = -__int_as_float(0x7F7FFFFF);
        float mx1 = mx0;
#pragma unroll
        for (int kk = 0; kk < 16; kk++) {
            mx0 = fmaxf(mx0, sH0[ch * 256 + ml * 16 + kk]);
            mx1 = fmaxf(mx1, sH1[ch * 256 + ml * 16 + kk]);
        }
        size_t base = (size_t)b * 256;
        out[(base + 64  + ch) * SS + m0 + ml] = mx1;            // ch 64..127
        out[(base + 128 + ch) * SS + m0 + ml] = mx0;            // ch 128..191
        out[(base + 192 + ch) * SS + m0 + ml] = sC[ch * 16 + ml]; // ch 192..255
    }
}

// ============================================================================
extern "C" void kernel_launch(void* const* d_in, const int* in_sizes, int n_in,
                              void* d_out, int out_size)
{
    const float* x   = (const float*)d_in[0];
    const float* xyz = (const float*)d_in[1];
    const float* W0  = (const float*)d_in[2];
    const float* b0  = (const float*)d_in[3];
    const float* W1  = (const float*)d_in[4];
    const float* b1  = (const float*)d_in[5];
    const float* W2  = (const float*)d_in[6];
    const float* b2  = (const float*)d_in[7];
    float* out = (float*)d_out;

    cudaFuncSetAttribute(fps_kernel,
                         cudaFuncAttributeMaxDynamicSharedMemorySize, 131072);
    cudaFuncSetAttribute(knn_gemm_kernel,
                         cudaFuncAttributeMaxDynamicSharedMemorySize, 65536);
    cudaFuncSetAttribute(edge_kernel,
                         cudaFuncAttributeMaxDynamicSharedMemorySize, 172032);

    fps_kernel<<<BB, 512, 131072>>>(xyz, out);
    gather_kernel<<<(BB * CC * SS + 255) / 256, 256>>>(x);
    norms_kernel<<<(BB * NN + BB * SS + 255) / 256, 256>>>(x);
    knn_gemm_kernel<<<dim3(NN / 128, SS / 128, BB), 256, 65536>>>(x);
    topk_kernel<<<BB * SS / 8, 256>>>();
    edge_kernel<<<BB * SS / 16, 256, 172032>>>(x, W0, b0, W1, b1, W2, b2, out);
}